// round 16
// baseline (speedup 1.0000x reference)
#include <cuda_runtime.h>
#include <cuda_fp16.h>
#include <cstdint>

#define B_    32
#define NHEAD 8
#define NPIX  (B_*64*64)       /* 131072 */
#define NOUT  (B_*32*32)       /* 32768  */

__device__ float d_s0[NHEAD*16];
__device__ float d_qv[NHEAD];
__device__ float d_g[(size_t)NPIX*NHEAD];
__device__ float d_denom[B_*NHEAD];
__device__ __half d_v[(size_t)NPIX*256];          /* v in fp16, UNscaled */
__device__ __half d_acc[(size_t)NOUT*256];        /* gathered acc, fp16 */
__device__ __half d_B1[65536], d_B2[65536];       /* W^T [n][k], fp16 */

// ---------------------------------------------------------------- helpers
__device__ __forceinline__ uint32_t smem_u32(const void* p) {
    uint32_t a;
    asm("{ .reg .u64 t; cvta.to.shared.u64 t, %1; cvt.u32.u64 %0, t; }" : "=r"(a) : "l"(p));
    return a;
}
__device__ __forceinline__ void ldm_x4(uint32_t* r, uint32_t addr) {
    asm volatile("ldmatrix.sync.aligned.m8n8.x4.shared.b16 {%0,%1,%2,%3}, [%4];"
        : "=r"(r[0]), "=r"(r[1]), "=r"(r[2]), "=r"(r[3]) : "r"(addr));
}
__device__ __forceinline__ void mma_f16(float* c, const uint32_t* a, const uint32_t* b) {
    asm volatile("mma.sync.aligned.m16n8k16.row.col.f32.f16.f16.f32 "
        "{%0,%1,%2,%3}, {%4,%5,%6,%7}, {%8,%9}, {%0,%1,%2,%3};"
        : "+f"(c[0]), "+f"(c[1]), "+f"(c[2]), "+f"(c[3])
        : "r"(a[0]), "r"(a[1]), "r"(a[2]), "r"(a[3]), "r"(b[0]), "r"(b[1]));
}
__device__ __forceinline__ void cpa16(uint32_t dst, const void* src) {
    asm volatile("cp.async.ca.shared.global [%0], [%1], 16;" :: "r"(dst), "l"(src) : "memory");
}
#define CP_COMMIT() asm volatile("cp.async.commit_group;" ::: "memory")
#define CP_WAIT0()  asm volatile("cp.async.wait_group 0;" ::: "memory")
#define CP_WAIT1()  asm volatile("cp.async.wait_group 1;" ::: "memory")

__device__ __forceinline__ uint32_t pack16(float a, float b) {
    return (uint32_t)__half_as_ushort(__float2half_rn(a)) |
           ((uint32_t)__half_as_ushort(__float2half_rn(b)) << 16);
}

// ---------------------------------------------------------------------------
// KP: merged prep. Blocks 0..127: weight transpose to fp16. Block 128: s0/qv/denom.
// ---------------------------------------------------------------------------
__global__ void kp_prep(const float* __restrict__ w1, const float* __restrict__ w2,
                        const float* __restrict__ ne,
                        const float* __restrict__ wkq_w,
                        const float* __restrict__ wkq_b,
                        const float* __restrict__ wgactq_w,
                        const float* __restrict__ wgactq_b) {
    int t = threadIdx.x;
    if (blockIdx.x < 128) {
        int g = blockIdx.x * 256 + t;            // 0..32767
        int mat = g >> 14;
        int r = g & 16383;
        int n = r & 255;
        int k0 = (r >> 8) * 4;
        const float* W = mat ? w2 : w1;
        __half* T = mat ? d_B2 : d_B1;
        float x0 = W[(k0+0)*256 + n], x1 = W[(k0+1)*256 + n];
        float x2 = W[(k0+2)*256 + n], x3 = W[(k0+3)*256 + n];
        *(uint2*)(T + n*256 + k0) = make_uint2(pack16(x0, x1), pack16(x2, x3));
        return;
    }
    // block 128: tiny prep
    __shared__ float sq[128];
    __shared__ float sk[16][8];
    d_denom[t] = 0.f;
    if (t < 128) {
        float acc = wkq_b[128 + t];
        #pragma unroll 8
        for (int m = 0; m < 128; m++) acc += ne[m] * wkq_w[m*256 + 128 + t];
        sq[t] = acc;
    } else {
        int idx = t - 128, n = idx >> 3, h = idx & 7, col = h * 16;
        const float* nerow = ne + n*128;
        float acc = wkq_b[col];
        #pragma unroll 8
        for (int m = 0; m < 128; m++) acc += nerow[m] * wkq_w[m*256 + col];
        sk[n][h] = acc;
    }
    __syncthreads();
    if (t < 8) {
        float l[16], mx = -1e30f;
        #pragma unroll
        for (int j = 0; j < 16; j++) { l[j] = sq[t*16 + j] + sk[j][t]; mx = fmaxf(mx, l[j]); }
        float s = 0.f;
        #pragma unroll
        for (int j = 0; j < 16; j++) { l[j] = expf(l[j] - mx); s += l[j]; }
        #pragma unroll
        for (int j = 0; j < 16; j++) d_s0[t*16 + j] = l[j] / s;
    } else if (t < 16) {
        int nh = t - 8;
        const float* nerow = ne + 14*128;
        float acc = wgactq_b[nh];
        #pragma unroll 8
        for (int m = 0; m < 128; m++) acc += nerow[m] * wgactq_w[m*8 + nh];
        d_qv[nh] = acc;
    }
}

// ---------------------------------------------------------------------------
// mma.sync fp16 single-product GEMM. Block 128x256, 16 warps (32x64),
// K-step 32, double-buffered smem.
// MODE 0: A = fp32 inps staged via cp.async, fp16-converted in-loop;
//         v out fp16, UNscaled. Blocks >= 1024 run the fused k1 gating pass.
// MODE 1: A = fp16 (d_acc) via cp.async; fp32 out.
// ---------------------------------------------------------------------------
#define SA_   0
#define SB_   10240
#define BUFSTR 30720
#define SSTG  (2*BUFSTR)             /* fp32 staging: 2 x 16384 */
#define SBIAS (SSTG + 32768)
#define SMT   (SBIAS + 1024)

template<int MODE>
__global__ void __launch_bounds__(512) gemm_mma(const float* __restrict__ Afp,
                                                const float* __restrict__ bias,
                                                float* __restrict__ outp,
                                                const float* __restrict__ wk,
                                                const float* __restrict__ wkb) {
    extern __shared__ char smc[];

    // ---- fused k1 gating blocks (MODE 0, bid >= 1024) ----
    if (MODE == 0 && blockIdx.x >= 1024) {
        float* sw   = (float*)smc;                 // 8KB: sw[nh*256 + c]
        float* sden = (float*)(smc + 8192);
        int t = threadIdx.x;
        for (int i = t; i < 2048; i += 512) {
            int c = i >> 3, nh = i & 7;
            sw[nh*256 + c] = wk[i];
        }
        if (t < 8) sden[t] = 0.f;
        __syncthreads();
        int blk = blockIdx.x - 1024;               // 0..255
        int pix0 = blk * 512;
        int b = pix0 >> 12;
        int lane = t & 31, warp = t >> 5;          // 16 warps
        for (int it = warp; it < 512; it += 16) {
            int p = pix0 + it;
            const float* row = Afp + (size_t)p * 256;
            float acc[8];
            #pragma unroll
            for (int n = 0; n < 8; n++) acc[n] = 0.f;
            #pragma unroll
            for (int q = 0; q < 8; q++) {
                float xv = row[lane + 32*q];
                #pragma unroll
                for (int n = 0; n < 8; n++) acc[n] += xv * sw[n*256 + lane + 32*q];
            }
            #pragma unroll
            for (int off = 16; off; off >>= 1)
                #pragma unroll
                for (int n = 0; n < 8; n++) acc[n] += __shfl_xor_sync(0xffffffffu, acc[n], off);
            if (lane < 8) {
                float gv = fmaxf(0.f, d_qv[lane] + acc[lane] + wkb[lane]);
                d_g[(size_t)p*8 + lane] = gv;
                atomicAdd(&sden[lane], gv);
            }
        }
        __syncthreads();
        if (t < 8) atomicAdd(&d_denom[b*8 + t], sden[t]);
        return;
    }

    const __half* Bg = (MODE == 0) ? d_B1 : d_B2;

    int t = threadIdx.x, lane = t & 31, wid = t >> 5;
    int wm = wid & 3, wn = wid >> 2;         // 4 x 4 warp grid, 32x64 tiles
    int bm = blockIdx.x * 128;
    uint32_t sb = smem_u32(smc);

    float* sbias = (float*)(smc + SBIAS);
    if (t < 256) sbias[t] = bias[t];

    auto issue = [&](int kc, int buf) {
        uint32_t base = sb + buf * BUFSTR;
        if (MODE == 0) {
            uint32_t stg = sb + SSTG + buf * 16384;
            #pragma unroll
            for (int j = 0; j < 2; j++) {
                int idx = t + 512*j;
                int row = idx >> 3, seg = idx & 7;
                cpa16(stg + (uint32_t)idx * 16,
                      Afp + (size_t)(bm + row) * 256 + kc * 32 + seg * 4);
            }
        } else {
            int arow = t >> 2, aseg = t & 3;
            uint32_t dstA = (uint32_t)(arow * 80 + aseg * 16);
            cpa16(base + SA_ + dstA, d_acc + (size_t)(bm + arow) * 256 + kc * 32 + aseg * 8);
        }
        #pragma unroll
        for (int j = 0; j < 2; j++) {
            int idx = t + 512 * j;
            int brow = idx >> 2, bseg = idx & 3;
            uint32_t dstB = (uint32_t)(brow * 80 + bseg * 16);
            cpa16(base + SB_ + dstB, Bg + (size_t)brow * 256 + kc * 32 + bseg * 8);
        }
        CP_COMMIT();
    };

    auto convertA = [&](int kc) {
        if (MODE != 0) return;
        int buf = kc & 1;
        const char* stg = smc + SSTG + buf * 16384;
        #pragma unroll
        for (int j = 0; j < 2; j++) {
            int idx = t + 512*j;
            int row = idx >> 3, c4 = idx & 7;
            float4 x = *(const float4*)(stg + (size_t)idx * 16);
            uint32_t off = (uint32_t)(buf * BUFSTR + row * 80 + c4 * 8);
            *(uint2*)(smc + SA_ + off) = make_uint2(pack16(x.x, x.y), pack16(x.z, x.w));
        }
    };

    int mat = lane >> 3, r8 = lane & 7;
    uint32_t aBase = (uint32_t)((wm*32 + (mat & 1)*8 + r8) * 80 + ((mat >> 1)*8) * 2);
    uint32_t bBase = (uint32_t)((wn*64 + (mat >> 1)*8 + r8) * 80 + ((mat & 1)*8) * 2);

    float acc[2][8][4];
    #pragma unroll
    for (int i = 0; i < 2; i++)
        #pragma unroll
        for (int j = 0; j < 8; j++)
            #pragma unroll
            for (int q = 0; q < 4; q++) acc[i][j][q] = 0.f;

    issue(0, 0);
    issue(1, 1);
    CP_WAIT1();                 // group 0 arrived
    __syncthreads();
    convertA(0);
    __syncthreads();

    #pragma unroll
    for (int ks = 0; ks < 8; ks++) {
        int buf = ks & 1;
        uint32_t abuf = sb + buf * BUFSTR;

        #pragma unroll
        for (int kk = 0; kk < 2; kk++) {
            uint32_t kb = kk * 32;
            uint32_t ah[2][4];
            #pragma unroll
            for (int mt = 0; mt < 2; mt++)
                ldm_x4(ah[mt], abuf + SA_ + aBase + mt*16*80 + kb);
            #pragma unroll
            for (int h = 0; h < 2; h++) {
                uint32_t bh[4][2];
                #pragma unroll
                for (int pp = 0; pp < 2; pp++) {
                    int p = 2*h + pp;
                    uint32_t tmp[4];
                    ldm_x4(tmp, abuf + SB_ + bBase + p*16*80 + kb);
                    bh[2*pp][0] = tmp[0]; bh[2*pp][1] = tmp[1];
                    bh[2*pp+1][0] = tmp[2]; bh[2*pp+1][1] = tmp[3];
                }
                #pragma unroll
                for (int mt = 0; mt < 2; mt++)
                    #pragma unroll
                    for (int nn = 0; nn < 4; nn++)
                        mma_f16(acc[mt][4*h + nn], ah[mt], bh[nn]);
            }
        }
        __syncthreads();                       // MMA reads done before refill

        if (ks < 6) issue(ks + 2, buf);        // refill buffer just freed
        if (ks < 7) {
            if (ks < 6) { CP_WAIT1(); } else { CP_WAIT0(); }   // group ks+1 arrived
            __syncthreads();
            convertA(ks + 1);
            __syncthreads();
        }
    }

    // epilogue (no act scaling in MODE 0 — moved to gather)
    #pragma unroll
    for (int mt = 0; mt < 2; mt++) {
        #pragma unroll
        for (int hf = 0; hf < 2; hf++) {
            int row = bm + wm*32 + mt*16 + hf*8 + (lane >> 2);
            #pragma unroll
            for (int nt = 0; nt < 8; nt++) {
                int col = wn*64 + nt*8 + (lane & 3)*2;
                float v0 = acc[mt][nt][hf*2+0] + sbias[col];
                float v1 = acc[mt][nt][hf*2+1] + sbias[col + 1];
                if (MODE == 0) {
                    *(uint32_t*)(d_v + (size_t)row * 256 + col) = pack16(v0, v1);
                } else {
                    *(float2*)(outp + (size_t)row * 256 + col) = make_float2(v0, v1);
                }
            }
        }
    }
}

// ---------------------------------------------------------------------------
// K4a: patch gather with fused act scaling.
// uint4 loads (8 ch/thread), 2x4 output tile per block, fp32 accumulate.
// tap weight = s0[n] * g[tap_pixel, h] * 4096/(denom[b,h]+eps)
// ---------------------------------------------------------------------------
__global__ void __launch_bounds__(256) k4a_gather() {
    __shared__ float ss0[128];
    int t = threadIdx.x;
    if (t < 128) ss0[t] = d_s0[t];
    __syncthreads();

    int op = blockIdx.x;                    // 0..4095
    int b  = op >> 7;                       // 32 batches, 128 blocks each
    int xt = (op >> 3) & 15, yt = op & 7;   // 16 x 8 tiles of 2x4 outputs
    int out = t >> 5;                       // 0..7
    int x = 2*xt + (out >> 2);
    int y = 4*yt + (out & 3);
    int c8 = t & 31;                        // 8-channel group index
    int h = c8 >> 2;

    float invd = 4096.f / (d_denom[b*8 + h] + 1e-6f);

    float s[16];
    #pragma unroll
    for (int n = 0; n < 16; n++) s[n] = ss0[h*16 + n] * invd;

    float a8[8];
    #pragma unroll
    for (int q = 0; q < 8; q++) a8[q] = 0.f;

    #pragma unroll
    for (int i = 0; i < 4; i++) {
        int sh = 2*x + i - 1;
        if ((unsigned)sh >= 64u) continue;
        #pragma unroll
        for (int j = 0; j < 4; j++) {
            int sw = 2*y + j - 1;
            if ((unsigned)sw >= 64u) continue;
            size_t pix = ((size_t)b*64 + sh)*64 + sw;
            float w = s[i*4 + j] * __ldg(&d_g[pix*8 + h]);
            uint4 raw = *(const uint4*)(d_v + pix*256 + c8*8);
            float2 p0 = __half22float2(*(__half2*)&raw.x);
            float2 p1 = __half22float2(*(__half2*)&raw.y);
            float2 p2 = __half22float2(*(__half2*)&raw.z);
            float2 p3 = __half22float2(*(__half2*)&raw.w);
            a8[0] += w * p0.x; a8[1] += w * p0.y;
            a8[2] += w * p1.x; a8[3] += w * p1.y;
            a8[4] += w * p2.x; a8[5] += w * p2.y;
            a8[6] += w * p3.x; a8[7] += w * p3.y;
        }
    }

    size_t idx = ((size_t)((b*32 + x)*32 + y))*256 + c8*8;
    uint4 o;
    o.x = pack16(a8[0], a8[1]);
    o.y = pack16(a8[2], a8[3]);
    o.z = pack16(a8[4], a8[5]);
    o.w = pack16(a8[6], a8[7]);
    *(uint4*)(d_acc + idx) = o;
}

// ---------------------------------------------------------------------------
extern "C" void kernel_launch(void* const* d_in, const int* in_sizes, int n_in,
                              void* d_out, int out_size) {
    const float* inps     = (const float*)d_in[0];
    const float* ne       = (const float*)d_in[1];
    const float* wkq_w    = (const float*)d_in[2];
    const float* wkq_b    = (const float*)d_in[3];
    const float* wv_w     = (const float*)d_in[4];
    const float* wv_b     = (const float*)d_in[5];
    const float* wgactq_w = (const float*)d_in[6];
    const float* wgactq_b = (const float*)d_in[7];
    const float* wgactk_w = (const float*)d_in[8];
    const float* wgactk_b = (const float*)d_in[9];
    const float* wf_w     = (const float*)d_in[10];
    const float* wf_b     = (const float*)d_in[11];
    float* out = (float*)d_out;

    static int inited = 0;
    if (!inited) {
        cudaFuncSetAttribute(gemm_mma<0>, cudaFuncAttributeMaxDynamicSharedMemorySize, SMT);
        cudaFuncSetAttribute(gemm_mma<1>, cudaFuncAttributeMaxDynamicSharedMemorySize, SMT);
        inited = 1;
    }

    kp_prep<<<129, 256>>>(wv_w, wf_w, ne, wkq_w, wkq_b, wgactq_w, wgactq_b);
    gemm_mma<0><<<1280, 512, SMT>>>(inps, wv_b, nullptr, wgactk_w, wgactk_b);
    k4a_gather<<<4096, 256>>>();
    gemm_mma<1><<<256, 512, SMT>>>(nullptr, wf_b, out, nullptr, nullptr);
}

// round 17
// speedup vs baseline: 1.0172x; 1.0172x over previous
#include <cuda_runtime.h>
#include <cuda_fp16.h>
#include <cstdint>

#define B_    32
#define NHEAD 8
#define NPIX  (B_*64*64)       /* 131072 */
#define NOUT  (B_*32*32)       /* 32768  */

__device__ float d_s0[NHEAD*16];
__device__ float d_qv[NHEAD];
__device__ float d_g[(size_t)NPIX*NHEAD];
__device__ float d_denom[B_*NHEAD];
__device__ __half d_v[(size_t)NPIX*256];          /* v in fp16, UNscaled */
__device__ __half d_acc[(size_t)NOUT*256];        /* gathered acc, fp16 */
__device__ __half d_B1[65536], d_B2[65536];       /* W^T [n][k], fp16 */

// ---------------------------------------------------------------- helpers
__device__ __forceinline__ uint32_t smem_u32(const void* p) {
    uint32_t a;
    asm("{ .reg .u64 t; cvta.to.shared.u64 t, %1; cvt.u32.u64 %0, t; }" : "=r"(a) : "l"(p));
    return a;
}
__device__ __forceinline__ void ldm_x4(uint32_t* r, uint32_t addr) {
    asm volatile("ldmatrix.sync.aligned.m8n8.x4.shared.b16 {%0,%1,%2,%3}, [%4];"
        : "=r"(r[0]), "=r"(r[1]), "=r"(r[2]), "=r"(r[3]) : "r"(addr));
}
__device__ __forceinline__ void mma_f16(float* c, const uint32_t* a, const uint32_t* b) {
    asm volatile("mma.sync.aligned.m16n8k16.row.col.f32.f16.f16.f32 "
        "{%0,%1,%2,%3}, {%4,%5,%6,%7}, {%8,%9}, {%0,%1,%2,%3};"
        : "+f"(c[0]), "+f"(c[1]), "+f"(c[2]), "+f"(c[3])
        : "r"(a[0]), "r"(a[1]), "r"(a[2]), "r"(a[3]), "r"(b[0]), "r"(b[1]));
}
__device__ __forceinline__ void cpa16(uint32_t dst, const void* src) {
    asm volatile("cp.async.ca.shared.global [%0], [%1], 16;" :: "r"(dst), "l"(src) : "memory");
}
#define CP_COMMIT() asm volatile("cp.async.commit_group;" ::: "memory")
#define CP_WAIT0()  asm volatile("cp.async.wait_group 0;" ::: "memory")
#define CP_WAIT1()  asm volatile("cp.async.wait_group 1;" ::: "memory")

__device__ __forceinline__ uint32_t pack16(float a, float b) {
    return (uint32_t)__half_as_ushort(__float2half_rn(a)) |
           ((uint32_t)__half_as_ushort(__float2half_rn(b)) << 16);
}

// ---------------------------------------------------------------------------
// KP: merged prep. Blocks 0..127: weight transpose to fp16. Block 128: s0/qv/denom.
// ---------------------------------------------------------------------------
__global__ void kp_prep(const float* __restrict__ w1, const float* __restrict__ w2,
                        const float* __restrict__ ne,
                        const float* __restrict__ wkq_w,
                        const float* __restrict__ wkq_b,
                        const float* __restrict__ wgactq_w,
                        const float* __restrict__ wgactq_b) {
    int t = threadIdx.x;
    if (blockIdx.x < 128) {
        int g = blockIdx.x * 256 + t;            // 0..32767
        int mat = g >> 14;
        int r = g & 16383;
        int n = r & 255;
        int k0 = (r >> 8) * 4;
        const float* W = mat ? w2 : w1;
        __half* T = mat ? d_B2 : d_B1;
        float x0 = W[(k0+0)*256 + n], x1 = W[(k0+1)*256 + n];
        float x2 = W[(k0+2)*256 + n], x3 = W[(k0+3)*256 + n];
        *(uint2*)(T + n*256 + k0) = make_uint2(pack16(x0, x1), pack16(x2, x3));
        return;
    }
    // block 128: tiny prep
    __shared__ float sq[128];
    __shared__ float sk[16][8];
    d_denom[t] = 0.f;
    if (t < 128) {
        float acc = wkq_b[128 + t];
        #pragma unroll 8
        for (int m = 0; m < 128; m++) acc += ne[m] * wkq_w[m*256 + 128 + t];
        sq[t] = acc;
    } else {
        int idx = t - 128, n = idx >> 3, h = idx & 7, col = h * 16;
        const float* nerow = ne + n*128;
        float acc = wkq_b[col];
        #pragma unroll 8
        for (int m = 0; m < 128; m++) acc += nerow[m] * wkq_w[m*256 + col];
        sk[n][h] = acc;
    }
    __syncthreads();
    if (t < 8) {
        float l[16], mx = -1e30f;
        #pragma unroll
        for (int j = 0; j < 16; j++) { l[j] = sq[t*16 + j] + sk[j][t]; mx = fmaxf(mx, l[j]); }
        float s = 0.f;
        #pragma unroll
        for (int j = 0; j < 16; j++) { l[j] = expf(l[j] - mx); s += l[j]; }
        #pragma unroll
        for (int j = 0; j < 16; j++) d_s0[t*16 + j] = l[j] / s;
    } else if (t < 16) {
        int nh = t - 8;
        const float* nerow = ne + 14*128;
        float acc = wgactq_b[nh];
        #pragma unroll 8
        for (int m = 0; m < 128; m++) acc += nerow[m] * wgactq_w[m*8 + nh];
        d_qv[nh] = acc;
    }
}

// ---------------------------------------------------------------------------
// mma.sync fp16 GEMM, single sync per K-step (software pipelined).
// Block 128x256, 16 warps (32x64), K-step 32.
// A-bf16: 2 bufs (MODE 0, written by in-CTA convert) / 3 bufs (MODE 1, cp.async).
// B: 3 bufs (cp.async). fp32 A staging: 2 bufs, thread-self-consistent.
// MODE 0: blocks >= 1024 run the fused k1 gating pass instead.
// ---------------------------------------------------------------------------
#define SA3(i) ((i)*10240)
#define SB3(i) (30720 + (i)*20480)
#define SSTG   92160
#define SBIAS  124928
#define SMT    125952

template<int MODE>
__global__ void __launch_bounds__(512) gemm_mma(const float* __restrict__ Afp,
                                                const float* __restrict__ bias,
                                                float* __restrict__ outp,
                                                const float* __restrict__ wk,
                                                const float* __restrict__ wkb) {
    extern __shared__ char smc[];

    // ---- fused k1 gating blocks (MODE 0, bid >= 1024) ----
    if (MODE == 0 && blockIdx.x >= 1024) {
        float* sw   = (float*)smc;
        float* sden = (float*)(smc + 8192);
        int t = threadIdx.x;
        for (int i = t; i < 2048; i += 512) {
            int c = i >> 3, nh = i & 7;
            sw[nh*256 + c] = wk[i];
        }
        if (t < 8) sden[t] = 0.f;
        __syncthreads();
        int blk = blockIdx.x - 1024;               // 0..255
        int pix0 = blk * 512;
        int b = pix0 >> 12;
        int lane = t & 31, warp = t >> 5;
        for (int it = warp; it < 512; it += 16) {
            int p = pix0 + it;
            const float* row = Afp + (size_t)p * 256;
            float acc[8];
            #pragma unroll
            for (int n = 0; n < 8; n++) acc[n] = 0.f;
            #pragma unroll
            for (int q = 0; q < 8; q++) {
                float xv = row[lane + 32*q];
                #pragma unroll
                for (int n = 0; n < 8; n++) acc[n] += xv * sw[n*256 + lane + 32*q];
            }
            #pragma unroll
            for (int off = 16; off; off >>= 1)
                #pragma unroll
                for (int n = 0; n < 8; n++) acc[n] += __shfl_xor_sync(0xffffffffu, acc[n], off);
            if (lane < 8) {
                float gv = fmaxf(0.f, d_qv[lane] + acc[lane] + wkb[lane]);
                d_g[(size_t)p*8 + lane] = gv;
                atomicAdd(&sden[lane], gv);
            }
        }
        __syncthreads();
        if (t < 8) atomicAdd(&d_denom[b*8 + t], sden[t]);
        return;
    }

    const __half* Bg = (MODE == 0) ? d_B1 : d_B2;

    int t = threadIdx.x, lane = t & 31, wid = t >> 5;
    int wm = wid & 3, wn = wid >> 2;
    int bm = blockIdx.x * 128;
    uint32_t sb = smem_u32(smc);

    float* sbias = (float*)(smc + SBIAS);
    if (t < 256) sbias[t] = bias[t];

    auto issue = [&](int kc) {
        if (MODE == 0) {
            uint32_t stg = sb + SSTG + (kc & 1) * 16384;
            #pragma unroll
            for (int j = 0; j < 2; j++) {
                int idx = t + 512*j;
                int row = idx >> 3, seg = idx & 7;
                cpa16(stg + (uint32_t)idx * 16,
                      Afp + (size_t)(bm + row) * 256 + kc * 32 + seg * 4);
            }
        } else {
            uint32_t base = sb + SA3(kc % 3);
            int arow = t >> 2, aseg = t & 3;
            cpa16(base + (uint32_t)(arow * 80 + aseg * 16),
                  d_acc + (size_t)(bm + arow) * 256 + kc * 32 + aseg * 8);
        }
        uint32_t bbase = sb + SB3(kc % 3);
        #pragma unroll
        for (int j = 0; j < 2; j++) {
            int idx = t + 512 * j;
            int brow = idx >> 2, bseg = idx & 3;
            cpa16(bbase + (uint32_t)(brow * 80 + bseg * 16),
                  Bg + (size_t)brow * 256 + kc * 32 + bseg * 8);
        }
        CP_COMMIT();
    };

    // convert: each thread converts exactly the staging bytes IT cp.async'd
    // (self-visibility after wait_group; no barrier needed before this).
    auto convertA = [&](int kc) {
        if (MODE != 0) return;
        const char* stg = smc + SSTG + (kc & 1) * 16384;
        #pragma unroll
        for (int j = 0; j < 2; j++) {
            int idx = t + 512*j;
            int row = idx >> 3, c4 = idx & 7;
            float4 x = *(const float4*)(stg + (size_t)idx * 16);
            uint32_t off = (uint32_t)(SA3(kc & 1) + row * 80 + c4 * 8);
            *(uint2*)(smc + off) = make_uint2(pack16(x.x, x.y), pack16(x.z, x.w));
        }
    };

    int mat = lane >> 3, r8 = lane & 7;
    uint32_t aBase = (uint32_t)((wm*32 + (mat & 1)*8 + r8) * 80 + ((mat >> 1)*8) * 2);
    uint32_t bBase = (uint32_t)((wn*64 + (mat >> 1)*8 + r8) * 80 + ((mat & 1)*8) * 2);

    float acc[2][8][4];
    #pragma unroll
    for (int i = 0; i < 2; i++)
        #pragma unroll
        for (int j = 0; j < 8; j++)
            #pragma unroll
            for (int q = 0; q < 4; q++) acc[i][j][q] = 0.f;

    issue(0);
    issue(1);
    CP_WAIT1();                 // group 0 arrived (self-visible staging)
    convertA(0);

    #pragma unroll
    for (int ks = 0; ks < 8; ks++) {
        __syncthreads();        // single barrier: orders prior MMA reads,
                                // convert STS, and arrived cp.async data for all
        if (ks < 6) { issue(ks + 2); CP_WAIT1(); }
        else if (ks == 6) { CP_WAIT0(); }
        if (ks < 7) convertA(ks + 1);

        uint32_t abuf = sb + (MODE == 0 ? SA3(ks & 1) : SA3(ks % 3));
        uint32_t bbuf = sb + SB3(ks % 3);
        #pragma unroll
        for (int kk = 0; kk < 2; kk++) {
            uint32_t kb = kk * 32;
            uint32_t ah[2][4];
            #pragma unroll
            for (int mt = 0; mt < 2; mt++)
                ldm_x4(ah[mt], abuf + aBase + mt*16*80 + kb);
            #pragma unroll
            for (int h = 0; h < 2; h++) {
                uint32_t bh[4][2];
                #pragma unroll
                for (int pp = 0; pp < 2; pp++) {
                    int p = 2*h + pp;
                    uint32_t tmp[4];
                    ldm_x4(tmp, bbuf + bBase + p*16*80 + kb);
                    bh[2*pp][0] = tmp[0]; bh[2*pp][1] = tmp[1];
                    bh[2*pp+1][0] = tmp[2]; bh[2*pp+1][1] = tmp[3];
                }
                #pragma unroll
                for (int mt = 0; mt < 2; mt++)
                    #pragma unroll
                    for (int nn = 0; nn < 4; nn++)
                        mma_f16(acc[mt][4*h + nn], ah[mt], bh[nn]);
            }
        }
    }

    // epilogue (no act scaling in MODE 0 — lives in gather)
    #pragma unroll
    for (int mt = 0; mt < 2; mt++) {
        #pragma unroll
        for (int hf = 0; hf < 2; hf++) {
            int row = bm + wm*32 + mt*16 + hf*8 + (lane >> 2);
            #pragma unroll
            for (int nt = 0; nt < 8; nt++) {
                int col = wn*64 + nt*8 + (lane & 3)*2;
                float v0 = acc[mt][nt][hf*2+0] + sbias[col];
                float v1 = acc[mt][nt][hf*2+1] + sbias[col + 1];
                if (MODE == 0) {
                    *(uint32_t*)(d_v + (size_t)row * 256 + col) = pack16(v0, v1);
                } else {
                    *(float2*)(outp + (size_t)row * 256 + col) = make_float2(v0, v1);
                }
            }
        }
    }
}

// ---------------------------------------------------------------------------
// K4a: patch gather with fused act scaling.
// ---------------------------------------------------------------------------
__global__ void __launch_bounds__(256) k4a_gather() {
    __shared__ float ss0[128];
    int t = threadIdx.x;
    if (t < 128) ss0[t] = d_s0[t];
    __syncthreads();

    int op = blockIdx.x;                    // 0..4095
    int b  = op >> 7;
    int xt = (op >> 3) & 15, yt = op & 7;
    int out = t >> 5;
    int x = 2*xt + (out >> 2);
    int y = 4*yt + (out & 3);
    int c8 = t & 31;
    int h = c8 >> 2;

    float invd = 4096.f / (d_denom[b*8 + h] + 1e-6f);

    float s[16];
    #pragma unroll
    for (int n = 0; n < 16; n++) s[n] = ss0[h*16 + n] * invd;

    float a8[8];
    #pragma unroll
    for (int q = 0; q < 8; q++) a8[q] = 0.f;

    #pragma unroll
    for (int i = 0; i < 4; i++) {
        int sh = 2*x + i - 1;
        if ((unsigned)sh >= 64u) continue;
        #pragma unroll
        for (int j = 0; j < 4; j++) {
            int sw = 2*y + j - 1;
            if ((unsigned)sw >= 64u) continue;
            size_t pix = ((size_t)b*64 + sh)*64 + sw;
            float w = s[i*4 + j] * __ldg(&d_g[pix*8 + h]);
            uint4 raw = *(const uint4*)(d_v + pix*256 + c8*8);
            float2 p0 = __half22float2(*(__half2*)&raw.x);
            float2 p1 = __half22float2(*(__half2*)&raw.y);
            float2 p2 = __half22float2(*(__half2*)&raw.z);
            float2 p3 = __half22float2(*(__half2*)&raw.w);
            a8[0] += w * p0.x; a8[1] += w * p0.y;
            a8[2] += w * p1.x; a8[3] += w * p1.y;
            a8[4] += w * p2.x; a8[5] += w * p2.y;
            a8[6] += w * p3.x; a8[7] += w * p3.y;
        }
    }

    size_t idx = ((size_t)((b*32 + x)*32 + y))*256 + c8*8;
    uint4 o;
    o.x = pack16(a8[0], a8[1]);
    o.y = pack16(a8[2], a8[3]);
    o.z = pack16(a8[4], a8[5]);
    o.w = pack16(a8[6], a8[7]);
    *(uint4*)(d_acc + idx) = o;
}

// ---------------------------------------------------------------------------
extern "C" void kernel_launch(void* const* d_in, const int* in_sizes, int n_in,
                              void* d_out, int out_size) {
    const float* inps     = (const float*)d_in[0];
    const float* ne       = (const float*)d_in[1];
    const float* wkq_w    = (const float*)d_in[2];
    const float* wkq_b    = (const float*)d_in[3];
    const float* wv_w     = (const float*)d_in[4];
    const float* wv_b     = (const float*)d_in[5];
    const float* wgactq_w = (const float*)d_in[6];
    const float* wgactq_b = (const float*)d_in[7];
    const float* wgactk_w = (const float*)d_in[8];
    const float* wgactk_b = (const float*)d_in[9];
    const float* wf_w     = (const float*)d_in[10];
    const float* wf_b     = (const float*)d_in[11];
    float* out = (float*)d_out;

    static int inited = 0;
    if (!inited) {
        cudaFuncSetAttribute(gemm_mma<0>, cudaFuncAttributeMaxDynamicSharedMemorySize, SMT);
        cudaFuncSetAttribute(gemm_mma<1>, cudaFuncAttributeMaxDynamicSharedMemorySize, SMT);
        inited = 1;
    }

    kp_prep<<<129, 256>>>(wv_w, wf_w, ne, wkq_w, wkq_b, wgactq_w, wgactq_b);
    gemm_mma<0><<<1280, 512, SMT>>>(inps, wv_b, nullptr, wgactk_w, wgactk_b);
    k4a_gather<<<4096, 256>>>();
    gemm_mma<1><<<256, 512, SMT>>>(nullptr, wf_b, out, nullptr, nullptr);
}